// round 2
// baseline (speedup 1.0000x reference)
#include <cuda_runtime.h>
#include <math.h>

// ---------------------------------------------------------------------------
// GAT_652835029007 — sparse dependency-pruned evaluation, round 2.
// Output = h2[node N-1] only. Pipeline: kP(init+precompute) -> k1 -> k2 ->
// k3(tiled GEMM x1 + fused ps/pd) -> k4(agg+LN+ELU) -> k5(warp-dot x2 +
// fused ps2/pd2) -> k6(final).
// ---------------------------------------------------------------------------

#define NNODE 20001
#define LASTN 20000
#define INF   256
#define HID   128
#define NH    4
#define HD    512
#define NB    2
#define NE    500000
#define NE4   (NE / 4)
#define BMW   626          // ceil(20001/32)
#define NOUT  520          // 512 main outputs + 4 ps + 4 pd

#define MAX_D2 4096
#define MAX_E1 131072
#define MAX_X1 8192
#define MAX_S1 4096
#define MAX_MATCH 1024

#define INV_SCALE 0.044194173824159216f   // 1/sqrt(512)

// ------------------------------- scratch -----------------------------------
__device__ int      g_d2_cnt[NB];
__device__ int      g_d2_dst[NB][MAX_D2];
__device__ unsigned g_s1_bm[NB][BMW];
__device__ unsigned g_x1_bm[NB][BMW];
__device__ int      g_s1_cnt[NB];
__device__ int      g_x1_cnt[NB];
__device__ int      g_s1_list[NB][MAX_S1];
__device__ int      g_x1_list[NB][MAX_X1];
__device__ int      g_s1_idx[NB][NNODE];
__device__ int      g_x1_idx[NB][NNODE];
__device__ int      g_e1_cnt[NB];
__device__ int      g_e1_src[NB][MAX_E1];
__device__ int      g_e1_dst[NB][MAX_E1];
__device__ float    g_x1v[NB][MAX_X1][HD];
__device__ float    g_ps1[NB][MAX_X1][NH];
__device__ float    g_pd1[NB][MAX_X1][NH];
__device__ float    g_hln[NB][MAX_S1][HD];
__device__ float    g_x2v[NB][MAX_S1][HD];
__device__ float    g_ps2[NB][MAX_S1][NH];
__device__ float    g_pd2[NB][MAX_S1][NH];
// precomputed attention projection vectors + fused biases
__device__ float    g_va1[8][INF];    // [0..3]=src heads, [4..7]=dst heads
__device__ float    g_va2[8][HD];
__device__ float    g_bias1[NOUT];
__device__ float    g_bias2[NOUT];

// ------------------------------- helpers -----------------------------------
__device__ __forceinline__ float warpsum(float v) {
#pragma unroll
    for (int off = 16; off; off >>= 1)
        v += __shfl_down_sync(0xffffffffu, v, off);
    return v;
}

__device__ __forceinline__ float blockreduce256(float v, float* sred) {
    int t = threadIdx.x;
    sred[t] = v; __syncthreads();
#pragma unroll
    for (int s = 128; s > 0; s >>= 1) {
        if (t < s) sred[t] += sred[t + s];
        __syncthreads();
    }
    float r = sred[0]; __syncthreads();
    return r;
}

__device__ __forceinline__ float blockreduce128(float v, float* sred) {
    int t = threadIdx.x;
    sred[t] = v; __syncthreads();
#pragma unroll
    for (int s = 64; s > 0; s >>= 1) {
        if (t < s) sred[t] += sred[t + s];
        __syncthreads();
    }
    float r = sred[0]; __syncthreads();
    return r;
}

__device__ __forceinline__ void x1_add(int b, int node) {
    unsigned m = 1u << (node & 31);
    unsigned old = atomicOr(&g_x1_bm[b][node >> 5], m);
    if (!(old & m)) {
        int p = atomicAdd(&g_x1_cnt[b], 1);
        if (p < MAX_X1) { g_x1_list[b][p] = node; g_x1_idx[b][node] = p; }
    }
}

// ------------------------------- kP ----------------------------------------
// block 0          : reset counters/bitmaps, seed LASTN, copy main biases
// blocks 1..8      : g_va1[idx] = W1[h]^T a1[h, sd-half];  bias1[512+idx]
// blocks 9..16     : g_va2[idx] = W2[h]^T a2[h, sd-half];  bias2[512+idx]
__global__ void kP_pre(const float* __restrict__ W1, const float* __restrict__ b1,
                       const float* __restrict__ a1,
                       const float* __restrict__ W2, const float* __restrict__ b2,
                       const float* __restrict__ a2) {
    int t = threadIdx.x;
    int bid = blockIdx.x;
    __shared__ float sa[128];
    __shared__ float s_red[256];

    if (bid == 0) {
        for (int b = 0; b < NB; b++)
            for (int i = t; i < BMW; i += 256) {
                g_s1_bm[b][i] = 0u; g_x1_bm[b][i] = 0u;
            }
        for (int i = t; i < 512; i += 256) {
            g_bias1[i] = b1[i];
            g_bias2[i] = b2[i];
        }
        __syncthreads();
        if (t == 0) {
            for (int b = 0; b < NB; b++) {
                g_d2_cnt[b] = 0; g_e1_cnt[b] = 0;
                g_s1_cnt[b] = 1; g_x1_cnt[b] = 1;
                g_s1_list[b][0] = LASTN; g_s1_idx[b][LASTN] = 0;
                g_x1_list[b][0] = LASTN; g_x1_idx[b][LASTN] = 0;
                g_s1_bm[b][LASTN >> 5] |= 1u << (LASTN & 31);
                g_x1_bm[b][LASTN >> 5] |= 1u << (LASTN & 31);
            }
        }
        return;
    }
    if (bid <= 8) {
        int idx = bid - 1;           // sd*4 + h
        int sd = idx >> 2, h = idx & 3;
        if (t < 128) sa[t] = a1[h * 256 + sd * 128 + t];
        __syncthreads();
        // t = k in 0..255
        const float* Wh = W1 + (size_t)h * 128 * 256;
        float acc = 0.f;
#pragma unroll 8
        for (int o = 0; o < 128; o++) acc += Wh[o * 256 + t] * sa[o];
        g_va1[idx][t] = acc;
        float pv = (t < 128) ? b1[h * 128 + t] * sa[t] : 0.f;
        float c = blockreduce256(pv, s_red);
        if (t == 0) g_bias1[512 + idx] = c;
        return;
    }
    {
        int idx = bid - 9;
        int sd = idx >> 2, h = idx & 3;
        if (t < 128) sa[t] = a2[h * 256 + sd * 128 + t];
        __syncthreads();
        const float* Wh = W2 + (size_t)h * 128 * 512;
#pragma unroll
        for (int kk = 0; kk < 2; kk++) {
            int k = t + 256 * kk;
            float acc = 0.f;
#pragma unroll 8
            for (int o = 0; o < 128; o++) acc += Wh[o * 512 + k] * sa[o];
            g_va2[idx][k] = acc;
        }
        float pv = (t < 128) ? b2[h * 128 + t] * sa[t] : 0.f;
        float c = blockreduce256(pv, s_red);
        if (t == 0) g_bias2[512 + idx] = c;
        return;
    }
}

// ------------------------------- k1/k2 scans --------------------------------
__device__ __forceinline__ void k1_hit(int b, const int* base, int idx) {
    int dst = base[NE + idx];
    int p = atomicAdd(&g_d2_cnt[b], 1);
    if (p < MAX_D2) g_d2_dst[b][p] = dst;
    unsigned m = 1u << (dst & 31);
    unsigned old = atomicOr(&g_s1_bm[b][dst >> 5], m);
    if (!(old & m)) {
        int q = atomicAdd(&g_s1_cnt[b], 1);
        if (q < MAX_S1) { g_s1_list[b][q] = dst; g_s1_idx[b][dst] = q; }
        x1_add(b, dst);
    }
}

__global__ void k1_scan_out(const int* __restrict__ eo) {
    int b = blockIdx.y;
    int i4 = blockIdx.x * blockDim.x + threadIdx.x;
    if (i4 >= NE4) return;
    const int* base = eo + (size_t)b * 2 * NE;
    int4 s = ((const int4*)base)[i4];
    int i = i4 * 4;
    if (s.x == LASTN) k1_hit(b, base, i + 0);
    if (s.y == LASTN) k1_hit(b, base, i + 1);
    if (s.z == LASTN) k1_hit(b, base, i + 2);
    if (s.w == LASTN) k1_hit(b, base, i + 3);
}

__device__ __forceinline__ void k2_hit(int b, const int* base, int idx, int src) {
    if ((g_s1_bm[b][src >> 5] >> (src & 31)) & 1u) {
        int dst = base[NE + idx];
        int p = atomicAdd(&g_e1_cnt[b], 1);
        if (p < MAX_E1) { g_e1_src[b][p] = src; g_e1_dst[b][p] = dst; }
        x1_add(b, dst);
    }
}

__global__ void k2_scan_in(const int* __restrict__ ei) {
    int b = blockIdx.y;
    int i4 = blockIdx.x * blockDim.x + threadIdx.x;
    if (i4 >= NE4) return;
    const int* base = ei + (size_t)b * 2 * NE;
    int4 s = ((const int4*)base)[i4];
    int i = i4 * 4;
    k2_hit(b, base, i + 0, s.x);
    k2_hit(b, base, i + 1, s.y);
    k2_hit(b, base, i + 2, s.z);
    k2_hit(b, base, i + 3, s.w);
}

// ------------------------------- k3: x1 GEMM --------------------------------
// C[M=cnt, N=520] = gather(embed)[M,256] @ B^T, B rows = W1 rows (0..511) and
// va1 rows (512..519). Tiles 64x64, K-tiles of 64, 4x4 micro-tiles.
__global__ void __launch_bounds__(256) k3_x1(const float* __restrict__ embed,
                                             const float* __restrict__ W1) {
    int b = blockIdx.z;
    int cnt = min(g_x1_cnt[b], MAX_X1);
    int y = blockIdx.y;                   // 0..8
    int t = threadIdx.x;
    int tx = t & 15, ty = t >> 4;
    __shared__ float As[64][68];
    __shared__ float Bs[64][68];
    __shared__ int   snode[64];

    for (int mc = blockIdx.x; mc * 64 < cnt; mc += gridDim.x) {
        __syncthreads();
        if (t < 64) {
            int id = mc * 64 + t;
            snode[t] = (id < cnt) ? g_x1_list[b][id] : -1;
        }
        __syncthreads();
        float acc[4][4];
#pragma unroll
        for (int i = 0; i < 4; i++)
#pragma unroll
            for (int j = 0; j < 4; j++) acc[i][j] = 0.f;

        for (int kt = 0; kt < 4; kt++) {
#pragma unroll
            for (int i = 0; i < 4; i++) {
                int f = t + 256 * i;
                int row = f >> 4, c4 = f & 15;
                int nd = snode[row];
                float4 v = make_float4(0.f, 0.f, 0.f, 0.f);
                if (nd >= 0)
                    v = ((const float4*)embed)[(size_t)nd * 64 + kt * 16 + c4];
                *(float4*)&As[row][c4 * 4] = v;
                int out = y * 64 + row;
                float4 w = make_float4(0.f, 0.f, 0.f, 0.f);
                if (out < 512)
                    w = ((const float4*)W1)[(size_t)out * 64 + kt * 16 + c4];
                else if (out < NOUT)
                    w = ((const float4*)g_va1[out - 512])[kt * 16 + c4];
                *(float4*)&Bs[row][c4 * 4] = w;
            }
            __syncthreads();
#pragma unroll 8
            for (int k = 0; k < 64; k++) {
                float a[4], bb[4];
#pragma unroll
                for (int i = 0; i < 4; i++) a[i] = As[ty * 4 + i][k];
#pragma unroll
                for (int j = 0; j < 4; j++) bb[j] = Bs[tx * 4 + j][k];
#pragma unroll
                for (int i = 0; i < 4; i++)
#pragma unroll
                    for (int j = 0; j < 4; j++) acc[i][j] += a[i] * bb[j];
            }
            __syncthreads();
        }
#pragma unroll
        for (int i = 0; i < 4; i++) {
            int id = mc * 64 + ty * 4 + i;
            if (id >= cnt) continue;
#pragma unroll
            for (int j = 0; j < 4; j++) {
                int out = y * 64 + tx * 4 + j;
                if (out >= NOUT) continue;
                float v = acc[i][j] + g_bias1[out];
                if (out < 512)      g_x1v[b][id][out] = v;
                else if (out < 516) g_ps1[b][id][out - 512] = v;
                else                g_pd1[b][id][out - 516] = v;
            }
        }
    }
}

// ------------------------------- k4: aggregation + LN + ELU -----------------
__global__ void k4_agg(const float* __restrict__ g1, const float* __restrict__ bn1) {
    int b = blockIdx.y;
    int scnt = min(g_s1_cnt[b], MAX_S1);
    int ecnt = min(g_e1_cnt[b], MAX_E1);
    int t = threadIdx.x;
    __shared__ float s_hp[HD];
    __shared__ float s_rs[NH];
    __shared__ int   s_mcnt;
    __shared__ int   s_md[MAX_MATCH];
    __shared__ float s_me[MAX_MATCH][NH];
    __shared__ float s_red[256];

    for (int p = blockIdx.x; p < scnt; p += gridDim.x) {
        __syncthreads();
        for (int u = t; u < HD; u += 256) s_hp[u] = 0.f;
        if (t == 0) s_mcnt = 0;
        int node = g_s1_list[b][p];
        int xn = g_x1_idx[b][node];
        float psn[NH];
#pragma unroll
        for (int h = 0; h < NH; h++) psn[h] = g_ps1[b][xn][h];
        __syncthreads();

        // collect matching edges + attention weights
        for (int i = t; i < ecnt; i += 256) {
            if (g_e1_src[b][i] == node) {
                int d = g_e1_dst[b][i];
                int xd = g_x1_idx[b][d];
                int m = atomicAdd(&s_mcnt, 1);
                if (m < MAX_MATCH) {
                    s_md[m] = xd;
#pragma unroll
                    for (int h = 0; h < NH; h++) {
                        float s = psn[h] + g_pd1[b][xd][h];
                        float l = s > 0.f ? s : 0.2f * s;
                        s_me[m][h] = __expf(l * INV_SCALE);
                    }
                }
            }
        }
        __syncthreads();
        int mc = min(s_mcnt, MAX_MATCH);
        if (t < NH) {
            float r = 0.f;
            for (int m = 0; m < mc; m++) r += s_me[m][t];
            s_rs[t] = (r == 0.f) ? 1.f : r;
        }
        __syncthreads();

        // weighted accumulation of x1[dst]
        for (int m = 0; m < mc; m++) {
            int xd = s_md[m];
            const float* xr = g_x1v[b][xd];
            for (int u = t; u < HD; u += 256)
                s_hp[u] += s_me[m][u >> 7] * xr[u];
        }
        __syncthreads();

        float v0 = s_hp[t] / s_rs[t >> 7];
        float v1 = s_hp[t + 256] / s_rs[(t + 256) >> 7];
        float mean = blockreduce256(v0 + v1, s_red) * (1.f / 512.f);
        float d0 = v0 - mean, d1 = v1 - mean;
        float var = blockreduce256(d0 * d0 + d1 * d1, s_red) * (1.f / 511.f);
        float inv = 1.f / (sqrtf(var) + 1e-6f);
        float y0 = g1[t] * d0 * inv + bn1[t];
        float y1 = g1[t + 256] * d1 * inv + bn1[t + 256];
        y0 = y0 > 0.f ? y0 : __expf(y0) - 1.f;
        y1 = y1 > 0.f ? y1 : __expf(y1) - 1.f;
        g_hln[b][p][t] = y0;
        g_hln[b][p][t + 256] = y1;
        __syncthreads();
    }
}

// ------------------------------- k5: x2 + ps2/pd2 ---------------------------
// Warp handles 2 outputs (out, out+264); loops s1 nodes, hln rows from L1.
#define K5BLK 33
__global__ void __launch_bounds__(256) k5_x2(const float* __restrict__ W2) {
    int b = blockIdx.y;
    int scnt = min(g_s1_cnt[b], MAX_S1);
    int w = blockIdx.x * 8 + (threadIdx.x >> 5);   // 0..263
    int lane = threadIdx.x & 31;

    int out0 = w;
    int out1 = w + 264;
    float4 wv0[4], wv1[4];
    const float4* br0 = (out0 < 512) ? (const float4*)(W2 + (size_t)out0 * HD)
                                     : (const float4*)g_va2[out0 - 512];
#pragma unroll
    for (int c = 0; c < 4; c++) wv0[c] = br0[lane + 32 * c];
    bool has1 = (out1 < NOUT);
    if (has1) {
        const float4* br1 = (out1 < 512) ? (const float4*)(W2 + (size_t)out1 * HD)
                                         : (const float4*)g_va2[out1 - 512];
#pragma unroll
        for (int c = 0; c < 4; c++) wv1[c] = br1[lane + 32 * c];
    }
    float bias0 = g_bias2[out0];
    float bias1 = has1 ? g_bias2[out1] : 0.f;

    for (int p = 0; p < scnt; p++) {
        const float4* xr = (const float4*)g_hln[b][p];
        float s0 = 0.f, s1 = 0.f;
#pragma unroll
        for (int c = 0; c < 4; c++) {
            float4 x = xr[lane + 32 * c];
            s0 += wv0[c].x * x.x + wv0[c].y * x.y + wv0[c].z * x.z + wv0[c].w * x.w;
            if (has1)
                s1 += wv1[c].x * x.x + wv1[c].y * x.y + wv1[c].z * x.z + wv1[c].w * x.w;
        }
        s0 = warpsum(s0);
        s1 = warpsum(s1);
        if (lane == 0) {
            float v0 = s0 + bias0;
            if (out0 < 512)      g_x2v[b][p][out0] = v0;
            else if (out0 < 516) g_ps2[b][p][out0 - 512] = v0;
            else                 g_pd2[b][p][out0 - 516] = v0;
            if (has1) {
                float v1 = s1 + bias1;
                if (out1 < 512)      g_x2v[b][p][out1] = v1;
                else if (out1 < 516) g_ps2[b][p][out1 - 512] = v1;
                else                 g_pd2[b][p][out1 - 516] = v1;
            }
        }
    }
}

// ------------------------------- k6: final ----------------------------------
__global__ void k6_final(const float* __restrict__ g2, const float* __restrict__ bn2,
                         const float* __restrict__ Vw, const float* __restrict__ Vb,
                         float* __restrict__ out) {
    int b = blockIdx.x;
    int o = threadIdx.x;   // 0..127
    __shared__ float s_red[128];
    int ec = min(g_d2_cnt[b], MAX_D2);

    float psl[NH];
#pragma unroll
    for (int h = 0; h < NH; h++) psl[h] = g_ps2[b][0][h];

    float hp[NH] = {0.f, 0.f, 0.f, 0.f};
    float rs[NH] = {0.f, 0.f, 0.f, 0.f};
    for (int i = 0; i < ec; i++) {
        int d = g_d2_dst[b][i];
        int pd = g_s1_idx[b][d];
#pragma unroll
        for (int h = 0; h < NH; h++) {
            float s = psl[h] + g_pd2[b][pd][h];
            float l = s > 0.f ? s : 0.2f * s;
            float e = __expf(l * INV_SCALE);
            rs[h] += e;
            hp[h] += e * g_x2v[b][pd][h * HID + o];
        }
    }
    float v = 0.f;
#pragma unroll
    for (int h = 0; h < NH; h++) {
        float r = rs[h];
        r = (r == 0.f) ? 1.f : r;
        v += hp[h] / r;
    }
    v *= 0.25f;

    float mean = blockreduce128(v, s_red) * (1.f / 128.f);
    float dv = v - mean;
    float var = blockreduce128(dv * dv, s_red) * (1.f / 127.f);
    float inv = 1.f / (sqrtf(var) + 1e-6f);
    float y = g2[o] * dv * inv + bn2[o];
    y = y > 0.f ? y : 0.f;

    float c0 = blockreduce128(y * Vw[o], s_red);
    float c1 = blockreduce128(y * Vw[HID + o], s_red);
    if (o == 0) {
        out[b * 2 + 0] = c0 + Vb[0];
        out[b * 2 + 1] = c1 + Vb[1];
    }
}

// ------------------------------- launcher ----------------------------------
extern "C" void kernel_launch(void* const* d_in, const int* in_sizes, int n_in,
                              void* d_out, int out_size) {
    const int*   edge_in  = (const int*)d_in[0];
    const int*   edge_out = (const int*)d_in[1];
    const float* embed    = (const float*)d_in[2];
    const float* W1       = (const float*)d_in[3];
    const float* b1       = (const float*)d_in[4];
    const float* a1       = (const float*)d_in[5];
    const float* g1       = (const float*)d_in[6];
    const float* bn1      = (const float*)d_in[7];
    const float* W2       = (const float*)d_in[8];
    const float* b2       = (const float*)d_in[9];
    const float* a2       = (const float*)d_in[10];
    const float* g2       = (const float*)d_in[11];
    const float* bn2      = (const float*)d_in[12];
    const float* Vw       = (const float*)d_in[13];
    const float* Vb       = (const float*)d_in[14];
    float* out = (float*)d_out;

    kP_pre<<<17, 256>>>(W1, b1, a1, W2, b2, a2);
    dim3 gscan((NE4 + 255) / 256, NB);
    k1_scan_out<<<gscan, 256>>>(edge_out);
    k2_scan_in<<<gscan, 256>>>(edge_in);
    k3_x1<<<dim3(12, 9, NB), 256>>>(embed, W1);
    k4_agg<<<dim3(64, NB), 256>>>(g1, bn1);
    k5_x2<<<dim3(K5BLK, NB), 256>>>(W2);
    k6_final<<<NB, 128>>>(g2, bn2, Vw, Vb, out);
}

// round 3
// speedup vs baseline: 1.2351x; 1.2351x over previous
#include <cuda_runtime.h>
#include <math.h>

// ---------------------------------------------------------------------------
// GAT_652835029007 — sparse dependency-pruned evaluation, round 3.
// Pipeline: kP(init+precompute) -> k1 -> k2 -> k3(K-major tiled GEMM, fused
// ps/pd) -> k4(agg+LN+ELU) -> k5(warp-dot x2 + fused ps2/pd2) -> k6(final).
// Round-3 change: k3 shared tiles stored K-major => no bank conflicts.
// ---------------------------------------------------------------------------

#define NNODE 20001
#define LASTN 20000
#define INF   256
#define HID   128
#define NH    4
#define HD    512
#define NB    2
#define NE    500000
#define NE4   (NE / 4)
#define BMW   626          // ceil(20001/32)
#define NOUT  520          // 512 main outputs + 4 ps + 4 pd

#define MAX_D2 4096
#define MAX_E1 131072
#define MAX_X1 8192
#define MAX_S1 4096
#define MAX_MATCH 1024

#define INV_SCALE 0.044194173824159216f   // 1/sqrt(512)

// ------------------------------- scratch -----------------------------------
__device__ int      g_d2_cnt[NB];
__device__ int      g_d2_dst[NB][MAX_D2];
__device__ unsigned g_s1_bm[NB][BMW];
__device__ unsigned g_x1_bm[NB][BMW];
__device__ int      g_s1_cnt[NB];
__device__ int      g_x1_cnt[NB];
__device__ int      g_s1_list[NB][MAX_S1];
__device__ int      g_x1_list[NB][MAX_X1];
__device__ int      g_s1_idx[NB][NNODE];
__device__ int      g_x1_idx[NB][NNODE];
__device__ int      g_e1_cnt[NB];
__device__ int      g_e1_src[NB][MAX_E1];
__device__ int      g_e1_dst[NB][MAX_E1];
__device__ float    g_x1v[NB][MAX_X1][HD];
__device__ float    g_ps1[NB][MAX_X1][NH];
__device__ float    g_pd1[NB][MAX_X1][NH];
__device__ float    g_hln[NB][MAX_S1][HD];
__device__ float    g_x2v[NB][MAX_S1][HD];
__device__ float    g_ps2[NB][MAX_S1][NH];
__device__ float    g_pd2[NB][MAX_S1][NH];
// precomputed attention projection vectors + fused biases
__device__ float    g_va1[8][INF];    // [0..3]=src heads, [4..7]=dst heads
__device__ float    g_va2[8][HD];
__device__ float    g_bias1[NOUT];
__device__ float    g_bias2[NOUT];

// ------------------------------- helpers -----------------------------------
__device__ __forceinline__ float warpsum(float v) {
#pragma unroll
    for (int off = 16; off; off >>= 1)
        v += __shfl_down_sync(0xffffffffu, v, off);
    return v;
}

__device__ __forceinline__ float blockreduce256(float v, float* sred) {
    int t = threadIdx.x;
    sred[t] = v; __syncthreads();
#pragma unroll
    for (int s = 128; s > 0; s >>= 1) {
        if (t < s) sred[t] += sred[t + s];
        __syncthreads();
    }
    float r = sred[0]; __syncthreads();
    return r;
}

__device__ __forceinline__ float blockreduce128(float v, float* sred) {
    int t = threadIdx.x;
    sred[t] = v; __syncthreads();
#pragma unroll
    for (int s = 64; s > 0; s >>= 1) {
        if (t < s) sred[t] += sred[t + s];
        __syncthreads();
    }
    float r = sred[0]; __syncthreads();
    return r;
}

__device__ __forceinline__ void x1_add(int b, int node) {
    unsigned m = 1u << (node & 31);
    unsigned old = atomicOr(&g_x1_bm[b][node >> 5], m);
    if (!(old & m)) {
        int p = atomicAdd(&g_x1_cnt[b], 1);
        if (p < MAX_X1) { g_x1_list[b][p] = node; g_x1_idx[b][node] = p; }
    }
}

// ------------------------------- kP ----------------------------------------
__global__ void kP_pre(const float* __restrict__ W1, const float* __restrict__ b1,
                       const float* __restrict__ a1,
                       const float* __restrict__ W2, const float* __restrict__ b2,
                       const float* __restrict__ a2) {
    int t = threadIdx.x;
    int bid = blockIdx.x;
    __shared__ float sa[128];
    __shared__ float s_red[256];

    if (bid == 0) {
        for (int b = 0; b < NB; b++)
            for (int i = t; i < BMW; i += 256) {
                g_s1_bm[b][i] = 0u; g_x1_bm[b][i] = 0u;
            }
        for (int i = t; i < 512; i += 256) {
            g_bias1[i] = b1[i];
            g_bias2[i] = b2[i];
        }
        __syncthreads();
        if (t == 0) {
            for (int b = 0; b < NB; b++) {
                g_d2_cnt[b] = 0; g_e1_cnt[b] = 0;
                g_s1_cnt[b] = 1; g_x1_cnt[b] = 1;
                g_s1_list[b][0] = LASTN; g_s1_idx[b][LASTN] = 0;
                g_x1_list[b][0] = LASTN; g_x1_idx[b][LASTN] = 0;
                g_s1_bm[b][LASTN >> 5] |= 1u << (LASTN & 31);
                g_x1_bm[b][LASTN >> 5] |= 1u << (LASTN & 31);
            }
        }
        return;
    }
    if (bid <= 8) {
        int idx = bid - 1;           // sd*4 + h
        int sd = idx >> 2, h = idx & 3;
        if (t < 128) sa[t] = a1[h * 256 + sd * 128 + t];
        __syncthreads();
        const float* Wh = W1 + (size_t)h * 128 * 256;
        float acc = 0.f;
#pragma unroll 8
        for (int o = 0; o < 128; o++) acc += Wh[o * 256 + t] * sa[o];
        g_va1[idx][t] = acc;
        float pv = (t < 128) ? b1[h * 128 + t] * sa[t] : 0.f;
        float c = blockreduce256(pv, s_red);
        if (t == 0) g_bias1[512 + idx] = c;
        return;
    }
    {
        int idx = bid - 9;
        int sd = idx >> 2, h = idx & 3;
        if (t < 128) sa[t] = a2[h * 256 + sd * 128 + t];
        __syncthreads();
        const float* Wh = W2 + (size_t)h * 128 * 512;
#pragma unroll
        for (int kk = 0; kk < 2; kk++) {
            int k = t + 256 * kk;
            float acc = 0.f;
#pragma unroll 8
            for (int o = 0; o < 128; o++) acc += Wh[o * 512 + k] * sa[o];
            g_va2[idx][k] = acc;
        }
        float pv = (t < 128) ? b2[h * 128 + t] * sa[t] : 0.f;
        float c = blockreduce256(pv, s_red);
        if (t == 0) g_bias2[512 + idx] = c;
        return;
    }
}

// ------------------------------- k1/k2 scans --------------------------------
__device__ __forceinline__ void k1_hit(int b, const int* base, int idx) {
    int dst = base[NE + idx];
    int p = atomicAdd(&g_d2_cnt[b], 1);
    if (p < MAX_D2) g_d2_dst[b][p] = dst;
    unsigned m = 1u << (dst & 31);
    unsigned old = atomicOr(&g_s1_bm[b][dst >> 5], m);
    if (!(old & m)) {
        int q = atomicAdd(&g_s1_cnt[b], 1);
        if (q < MAX_S1) { g_s1_list[b][q] = dst; g_s1_idx[b][dst] = q; }
        x1_add(b, dst);
    }
}

__global__ void k1_scan_out(const int* __restrict__ eo) {
    int b = blockIdx.y;
    int i4 = blockIdx.x * blockDim.x + threadIdx.x;
    if (i4 >= NE4) return;
    const int* base = eo + (size_t)b * 2 * NE;
    int4 s = ((const int4*)base)[i4];
    int i = i4 * 4;
    if (s.x == LASTN) k1_hit(b, base, i + 0);
    if (s.y == LASTN) k1_hit(b, base, i + 1);
    if (s.z == LASTN) k1_hit(b, base, i + 2);
    if (s.w == LASTN) k1_hit(b, base, i + 3);
}

__device__ __forceinline__ void k2_hit(int b, const int* base, int idx, int src) {
    if ((g_s1_bm[b][src >> 5] >> (src & 31)) & 1u) {
        int dst = base[NE + idx];
        int p = atomicAdd(&g_e1_cnt[b], 1);
        if (p < MAX_E1) { g_e1_src[b][p] = src; g_e1_dst[b][p] = dst; }
        x1_add(b, dst);
    }
}

__global__ void k2_scan_in(const int* __restrict__ ei) {
    int b = blockIdx.y;
    int i4 = blockIdx.x * blockDim.x + threadIdx.x;
    if (i4 >= NE4) return;
    const int* base = ei + (size_t)b * 2 * NE;
    int4 s = ((const int4*)base)[i4];
    int i = i4 * 4;
    k2_hit(b, base, i + 0, s.x);
    k2_hit(b, base, i + 1, s.y);
    k2_hit(b, base, i + 2, s.z);
    k2_hit(b, base, i + 3, s.w);
}

// ------------------------------- k3: x1 GEMM (K-major tiles) ----------------
// C[M=cnt, N=520] = gather(embed)[M,256] @ B^T.
// Shared tiles K-major: As[k][m], Bs[k][n], pad 4 -> conflict-free LDS.128.
__global__ void __launch_bounds__(256) k3_x1(const float* __restrict__ embed,
                                             const float* __restrict__ W1) {
    int b = blockIdx.z;
    int cnt = min(g_x1_cnt[b], MAX_X1);
    int y = blockIdx.y;                   // 0..8 (n-tile)
    int t = threadIdx.x;
    int tx = t & 15, ty = t >> 4;         // tx -> n, ty -> m
    __shared__ float As[64][68];
    __shared__ float Bs[64][68];
    __shared__ int   snode[64];

    int mc = blockIdx.x;
    if (mc * 64 >= cnt) return;

    if (t < 64) {
        int id = mc * 64 + t;
        snode[t] = (id < cnt) ? g_x1_list[b][id] : -1;
    }
    __syncthreads();

    float acc[4][4];
#pragma unroll
    for (int i = 0; i < 4; i++)
#pragma unroll
        for (int j = 0; j < 4; j++) acc[i][j] = 0.f;

    for (int kt = 0; kt < 4; kt++) {
        // load tiles, transposing to K-major in smem.
        // u = t + 256*i : row = u>>4? No — assign m/n = u & 63, k4 = u >> 6.
#pragma unroll
        for (int i = 0; i < 4; i++) {
            int u = t + 256 * i;
            int mn = u & 63;        // m or n within tile (consecutive in warp)
            int k4 = u >> 6;        // float4 index within K-tile: 0..15
            int nd = snode[mn];
            float4 v = make_float4(0.f, 0.f, 0.f, 0.f);
            if (nd >= 0)
                v = ((const float4*)embed)[(size_t)nd * 64 + kt * 16 + k4];
            As[k4 * 4 + 0][mn] = v.x;
            As[k4 * 4 + 1][mn] = v.y;
            As[k4 * 4 + 2][mn] = v.z;
            As[k4 * 4 + 3][mn] = v.w;
            int out = y * 64 + mn;
            float4 w = make_float4(0.f, 0.f, 0.f, 0.f);
            if (out < 512)
                w = ((const float4*)W1)[(size_t)out * 64 + kt * 16 + k4];
            else if (out < NOUT)
                w = ((const float4*)g_va1[out - 512])[kt * 16 + k4];
            Bs[k4 * 4 + 0][mn] = w.x;
            Bs[k4 * 4 + 1][mn] = w.y;
            Bs[k4 * 4 + 2][mn] = w.z;
            Bs[k4 * 4 + 3][mn] = w.w;
        }
        __syncthreads();
#pragma unroll 8
        for (int k = 0; k < 64; k++) {
            float4 a4 = *(const float4*)&As[k][ty * 4];
            float4 b4 = *(const float4*)&Bs[k][tx * 4];
            float a[4] = {a4.x, a4.y, a4.z, a4.w};
            float bb[4] = {b4.x, b4.y, b4.z, b4.w};
#pragma unroll
            for (int i = 0; i < 4; i++)
#pragma unroll
                for (int j = 0; j < 4; j++) acc[i][j] += a[i] * bb[j];
        }
        __syncthreads();
    }
#pragma unroll
    for (int i = 0; i < 4; i++) {
        int id = mc * 64 + ty * 4 + i;
        if (id >= cnt) continue;
#pragma unroll
        for (int j = 0; j < 4; j++) {
            int out = y * 64 + tx * 4 + j;
            if (out >= NOUT) continue;
            float v = acc[i][j] + g_bias1[out];
            if (out < 512)      g_x1v[b][id][out] = v;
            else if (out < 516) g_ps1[b][id][out - 512] = v;
            else                g_pd1[b][id][out - 516] = v;
        }
    }
}

// ------------------------------- k4: aggregation + LN + ELU -----------------
__global__ void k4_agg(const float* __restrict__ g1, const float* __restrict__ bn1) {
    int b = blockIdx.y;
    int scnt = min(g_s1_cnt[b], MAX_S1);
    int ecnt = min(g_e1_cnt[b], MAX_E1);
    int t = threadIdx.x;
    __shared__ float s_hp[HD];
    __shared__ float s_rs[NH];
    __shared__ int   s_mcnt;
    __shared__ int   s_md[MAX_MATCH];
    __shared__ float s_me[MAX_MATCH][NH];
    __shared__ float s_red[256];

    for (int p = blockIdx.x; p < scnt; p += gridDim.x) {
        __syncthreads();
        for (int u = t; u < HD; u += 256) s_hp[u] = 0.f;
        if (t == 0) s_mcnt = 0;
        int node = g_s1_list[b][p];
        int xn = g_x1_idx[b][node];
        float psn[NH];
#pragma unroll
        for (int h = 0; h < NH; h++) psn[h] = g_ps1[b][xn][h];
        __syncthreads();

        for (int i = t; i < ecnt; i += 256) {
            if (g_e1_src[b][i] == node) {
                int d = g_e1_dst[b][i];
                int xd = g_x1_idx[b][d];
                int m = atomicAdd(&s_mcnt, 1);
                if (m < MAX_MATCH) {
                    s_md[m] = xd;
#pragma unroll
                    for (int h = 0; h < NH; h++) {
                        float s = psn[h] + g_pd1[b][xd][h];
                        float l = s > 0.f ? s : 0.2f * s;
                        s_me[m][h] = __expf(l * INV_SCALE);
                    }
                }
            }
        }
        __syncthreads();
        int mc = min(s_mcnt, MAX_MATCH);
        if (t < NH) {
            float r = 0.f;
            for (int m = 0; m < mc; m++) r += s_me[m][t];
            s_rs[t] = (r == 0.f) ? 1.f : r;
        }
        __syncthreads();

        for (int m = 0; m < mc; m++) {
            int xd = s_md[m];
            const float* xr = g_x1v[b][xd];
            for (int u = t; u < HD; u += 256)
                s_hp[u] += s_me[m][u >> 7] * xr[u];
        }
        __syncthreads();

        float v0 = s_hp[t] / s_rs[t >> 7];
        float v1 = s_hp[t + 256] / s_rs[(t + 256) >> 7];
        float mean = blockreduce256(v0 + v1, s_red) * (1.f / 512.f);
        float d0 = v0 - mean, d1 = v1 - mean;
        float var = blockreduce256(d0 * d0 + d1 * d1, s_red) * (1.f / 511.f);
        float inv = 1.f / (sqrtf(var) + 1e-6f);
        float y0 = g1[t] * d0 * inv + bn1[t];
        float y1 = g1[t + 256] * d1 * inv + bn1[t + 256];
        y0 = y0 > 0.f ? y0 : __expf(y0) - 1.f;
        y1 = y1 > 0.f ? y1 : __expf(y1) - 1.f;
        g_hln[b][p][t] = y0;
        g_hln[b][p][t + 256] = y1;
        __syncthreads();
    }
}

// ------------------------------- k5: x2 + ps2/pd2 ---------------------------
#define K5BLK 33
__global__ void __launch_bounds__(256) k5_x2(const float* __restrict__ W2) {
    int b = blockIdx.y;
    int scnt = min(g_s1_cnt[b], MAX_S1);
    int w = blockIdx.x * 8 + (threadIdx.x >> 5);   // 0..263
    int lane = threadIdx.x & 31;

    int out0 = w;
    int out1 = w + 264;
    float4 wv0[4], wv1[4];
    const float4* br0 = (out0 < 512) ? (const float4*)(W2 + (size_t)out0 * HD)
                                     : (const float4*)g_va2[out0 - 512];
#pragma unroll
    for (int c = 0; c < 4; c++) wv0[c] = br0[lane + 32 * c];
    bool has1 = (out1 < NOUT);
    if (has1) {
        const float4* br1 = (out1 < 512) ? (const float4*)(W2 + (size_t)out1 * HD)
                                         : (const float4*)g_va2[out1 - 512];
#pragma unroll
        for (int c = 0; c < 4; c++) wv1[c] = br1[lane + 32 * c];
    }
    float bias0 = g_bias2[out0];
    float bias1 = has1 ? g_bias2[out1] : 0.f;

    for (int p = 0; p < scnt; p++) {
        const float4* xr = (const float4*)g_hln[b][p];
        float s0 = 0.f, s1 = 0.f;
#pragma unroll
        for (int c = 0; c < 4; c++) {
            float4 x = xr[lane + 32 * c];
            s0 += wv0[c].x * x.x + wv0[c].y * x.y + wv0[c].z * x.z + wv0[c].w * x.w;
            if (has1)
                s1 += wv1[c].x * x.x + wv1[c].y * x.y + wv1[c].z * x.z + wv1[c].w * x.w;
        }
        s0 = warpsum(s0);
        s1 = warpsum(s1);
        if (lane == 0) {
            float v0 = s0 + bias0;
            if (out0 < 512)      g_x2v[b][p][out0] = v0;
            else if (out0 < 516) g_ps2[b][p][out0 - 512] = v0;
            else                 g_pd2[b][p][out0 - 516] = v0;
            if (has1) {
                float v1 = s1 + bias1;
                if (out1 < 512)      g_x2v[b][p][out1] = v1;
                else if (out1 < 516) g_ps2[b][p][out1 - 512] = v1;
                else                 g_pd2[b][p][out1 - 516] = v1;
            }
        }
    }
}

// ------------------------------- k6: final ----------------------------------
__global__ void k6_final(const float* __restrict__ g2, const float* __restrict__ bn2,
                         const float* __restrict__ Vw, const float* __restrict__ Vb,
                         float* __restrict__ out) {
    int b = blockIdx.x;
    int o = threadIdx.x;   // 0..127
    __shared__ float s_red[128];
    int ec = min(g_d2_cnt[b], MAX_D2);

    float psl[NH];
#pragma unroll
    for (int h = 0; h < NH; h++) psl[h] = g_ps2[b][0][h];

    float hp[NH] = {0.f, 0.f, 0.f, 0.f};
    float rs[NH] = {0.f, 0.f, 0.f, 0.f};
    for (int i = 0; i < ec; i++) {
        int d = g_d2_dst[b][i];
        int pd = g_s1_idx[b][d];
#pragma unroll
        for (int h = 0; h < NH; h++) {
            float s = psl[h] + g_pd2[b][pd][h];
            float l = s > 0.f ? s : 0.2f * s;
            float e = __expf(l * INV_SCALE);
            rs[h] += e;
            hp[h] += e * g_x2v[b][pd][h * HID + o];
        }
    }
    float v = 0.f;
#pragma unroll
    for (int h = 0; h < NH; h++) {
        float r = rs[h];
        r = (r == 0.f) ? 1.f : r;
        v += hp[h] / r;
    }
    v *= 0.25f;

    float mean = blockreduce128(v, s_red) * (1.f / 128.f);
    float dv = v - mean;
    float var = blockreduce128(dv * dv, s_red) * (1.f / 127.f);
    float inv = 1.f / (sqrtf(var) + 1e-6f);
    float y = g2[o] * dv * inv + bn2[o];
    y = y > 0.f ? y : 0.f;

    float c0 = blockreduce128(y * Vw[o], s_red);
    float c1 = blockreduce128(y * Vw[HID + o], s_red);
    if (o == 0) {
        out[b * 2 + 0] = c0 + Vb[0];
        out[b * 2 + 1] = c1 + Vb[1];
    }
}

// ------------------------------- launcher ----------------------------------
extern "C" void kernel_launch(void* const* d_in, const int* in_sizes, int n_in,
                              void* d_out, int out_size) {
    const int*   edge_in  = (const int*)d_in[0];
    const int*   edge_out = (const int*)d_in[1];
    const float* embed    = (const float*)d_in[2];
    const float* W1       = (const float*)d_in[3];
    const float* b1       = (const float*)d_in[4];
    const float* a1       = (const float*)d_in[5];
    const float* g1       = (const float*)d_in[6];
    const float* bn1      = (const float*)d_in[7];
    const float* W2       = (const float*)d_in[8];
    const float* b2       = (const float*)d_in[9];
    const float* a2       = (const float*)d_in[10];
    const float* g2       = (const float*)d_in[11];
    const float* bn2      = (const float*)d_in[12];
    const float* Vw       = (const float*)d_in[13];
    const float* Vb       = (const float*)d_in[14];
    float* out = (float*)d_out;

    kP_pre<<<17, 256>>>(W1, b1, a1, W2, b2, a2);
    dim3 gscan((NE4 + 255) / 256, NB);
    k1_scan_out<<<gscan, 256>>>(edge_out);
    k2_scan_in<<<gscan, 256>>>(edge_in);
    // M chunks: ceil(MAX expected cnt ~700 / 64) -> launch enough for 2048 rows
    k3_x1<<<dim3(32, 9, NB), 256>>>(embed, W1);
    k4_agg<<<dim3(64, NB), 256>>>(g1, bn1);
    k5_x2<<<dim3(K5BLK, NB), 256>>>(W2);
    k6_final<<<NB, 128>>>(g2, bn2, Vw, Vb, out);
}

// round 4
// speedup vs baseline: 1.3805x; 1.1177x over previous
#include <cuda_runtime.h>
#include <math.h>

// ---------------------------------------------------------------------------
// GAT_652835029007 — round 4: single persistent fused kernel.
// Key algebra: edge aggregation is linear in x1, so
//   hp = (sum_e e*embed[dst]) @ W1^T + (sum_e e)*b1
// which removes the dense x1 GEMM entirely. Same for layer 2 with hln/W2.
// Phases separated by a hand-rolled monotonic grid barrier.
// ---------------------------------------------------------------------------

#define NNODE 20001
#define LASTN 20000
#define INF   256
#define HID   128
#define NH    4
#define HD    512
#define NB    2
#define NE    500000
#define NE4   125000
#define BMW   626
#define MAX_D2    1024
#define MAX_E1    65536
#define MAX_X1    4096
#define MAX_S1    1024
#define MAX_MATCH 1024
#define INV_SCALE 0.044194173824159216f   // 1/sqrt(512)

// ------------------------------- scratch -----------------------------------
__device__ unsigned g_bar;                       // zero-init; reset each replay
__device__ int      g_d2_cnt[NB];
__device__ int      g_d2_dst[NB][MAX_D2];
__device__ unsigned g_s1_bm[NB][BMW];
__device__ unsigned g_x1_bm[NB][BMW];
__device__ int      g_s1_cnt[NB], g_x1_cnt[NB];
__device__ int      g_s1_list[NB][MAX_S1], g_x1_list[NB][MAX_X1];
__device__ int      g_s1_idx[NB][NNODE], g_x1_idx[NB][NNODE];
__device__ int      g_e1_cnt[NB];
__device__ int      g_e1_src[NB][MAX_E1], g_e1_dst[NB][MAX_E1];
__device__ float    g_p1[NB][MAX_X1][8];         // [0..3]=ps1, [4..7]=pd1
__device__ float    g_hln[NB][MAX_S1][HD];
__device__ float    g_p2[NB][MAX_S1][8];
__device__ float    g_va1[8][INF];               // W1^T a1-half per (sd,h)
__device__ float    g_va2[8][HD];
__device__ float    g_vb1[8], g_vb2[8];          // b . a-half

// ------------------------------- helpers -----------------------------------
__device__ __forceinline__ float warpsum(float v) {
#pragma unroll
    for (int off = 16; off; off >>= 1)
        v += __shfl_down_sync(0xffffffffu, v, off);
    return v;
}

__device__ __forceinline__ float blockreduce256(float v, float* sred) {
    int t = threadIdx.x;
    sred[t] = v; __syncthreads();
#pragma unroll
    for (int s = 128; s > 0; s >>= 1) {
        if (t < s) sred[t] += sred[t + s];
        __syncthreads();
    }
    float r = sred[0]; __syncthreads();
    return r;
}

__device__ __forceinline__ void gbar(unsigned target) {
    __syncthreads();
    if (threadIdx.x == 0) {
        __threadfence();
        atomicAdd(&g_bar, 1u);
        while (*(volatile unsigned*)&g_bar < target) __nanosleep(64);
        __threadfence();
    }
    __syncthreads();
}

__device__ __forceinline__ void x1_add(int b, int node) {
    unsigned m = 1u << (node & 31);
    unsigned old = atomicOr(&g_x1_bm[b][node >> 5], m);
    if (!(old & m)) {
        int p = atomicAdd(&g_x1_cnt[b], 1);
        if (p < MAX_X1) { g_x1_list[b][p] = node; g_x1_idx[b][node] = p; }
    }
}

__device__ __forceinline__ void k1_hit(int b, const int* base, int idx) {
    int dst = base[NE + idx];
    int p = atomicAdd(&g_d2_cnt[b], 1);
    if (p < MAX_D2) g_d2_dst[b][p] = dst;
    unsigned m = 1u << (dst & 31);
    unsigned old = atomicOr(&g_s1_bm[b][dst >> 5], m);
    if (!(old & m)) {
        int q = atomicAdd(&g_s1_cnt[b], 1);
        if (q < MAX_S1) { g_s1_list[b][q] = dst; g_s1_idx[b][dst] = q; }
        x1_add(b, dst);
    }
}

__device__ __forceinline__ void k2_hit(int b, const int* base, int idx, int src) {
    if ((g_s1_bm[b][src >> 5] >> (src & 31)) & 1u) {
        int dst = base[NE + idx];
        int p = atomicAdd(&g_e1_cnt[b], 1);
        if (p < MAX_E1) { g_e1_src[b][p] = src; g_e1_dst[b][p] = dst; }
        x1_add(b, dst);
    }
}

__device__ __forceinline__ float dot44(float4 a, float4 b) {
    return a.x * b.x + a.y * b.y + a.z * b.z + a.w * b.w;
}

// ------------------------------- fused kernel -------------------------------
__global__ void __launch_bounds__(256) fused(
    const int* __restrict__ ei, const int* __restrict__ eo,
    const float* __restrict__ embed,
    const float* __restrict__ W1, const float* __restrict__ b1,
    const float* __restrict__ a1,
    const float* __restrict__ g1, const float* __restrict__ bn1,
    const float* __restrict__ W2, const float* __restrict__ b2,
    const float* __restrict__ a2,
    const float* __restrict__ g2, const float* __restrict__ bn2,
    const float* __restrict__ Vw, const float* __restrict__ Vb,
    float* __restrict__ out)
{
    int t = threadIdx.x;
    int lane = t & 31, wid = t >> 5;
    unsigned nb = gridDim.x;
    int gtid = blockIdx.x * 256 + t;
    int nth = nb * 256;
    int gw = blockIdx.x * 8 + wid;

    __shared__ float s_red[256];
    __shared__ float s_rs[NH], s_rsT[NH];
    __shared__ int   s_mcnt;
    __shared__ __align__(16) char s_mem[27 * 1024];
    int*   s_md = (int*)s_mem;                          // P4: [1024]
    float (*s_me)[NH] = (float(*)[NH])(s_mem + 4096);   // P4: [1024][4]
    float (*s_z)[INF] = (float(*)[INF])(s_mem + 20480); // P4: [4][256]
    float* s_ov = (float*)(s_mem + 24576);              // P4: [512]
    float (*s_z2)[HD] = (float(*)[HD])(s_mem);          // P6: [4][512]
    float* s_hp2 = (float*)(s_mem + 8192);              // P6: [512]

    // ================= P0: init + precompute va/vb ==========================
    for (int i = gtid; i < NB * BMW; i += nth) {
        int b = i / BMW, w = i - b * BMW;
        unsigned v = (w == (LASTN >> 5)) ? (1u << (LASTN & 31)) : 0u;
        g_s1_bm[b][w] = v; g_x1_bm[b][w] = v;
    }
    if (gtid == 0) {
        for (int b = 0; b < NB; b++) {
            g_d2_cnt[b] = 0; g_e1_cnt[b] = 0;
            g_s1_cnt[b] = 1; g_x1_cnt[b] = 1;
            g_s1_list[b][0] = LASTN; g_s1_idx[b][LASTN] = 0;
            g_x1_list[b][0] = LASTN; g_x1_idx[b][LASTN] = 0;
        }
    }
    for (int u = gtid; u < 8 * INF; u += nth) {          // va1
        int idx = u >> 8, k = u & 255;
        int h = idx & 3, sd = idx >> 2;
        const float* Wh = W1 + (size_t)h * HID * INF;
        const float* av = a1 + h * 2 * HID + sd * HID;
        float acc = 0.f;
        for (int o = 0; o < HID; o++) acc += Wh[o * INF + k] * av[o];
        g_va1[idx][k] = acc;
    }
    for (int u = gtid; u < 8 * HD; u += nth) {           // va2
        int idx = u >> 9, k = u & 511;
        int h = idx & 3, sd = idx >> 2;
        const float* Wh = W2 + (size_t)h * HID * HD;
        const float* av = a2 + h * 2 * HID + sd * HID;
        float acc = 0.f;
        for (int o = 0; o < HID; o++) acc += Wh[o * HD + k] * av[o];
        g_va2[idx][k] = acc;
    }
    if (gw < 16) {                                       // vb1/vb2
        int which = gw >> 3, idx = gw & 7;
        int h = idx & 3, sd = idx >> 2;
        const float* bb = (which ? b2 : b1) + h * HID;
        const float* av = (which ? a2 : a1) + h * 2 * HID + sd * HID;
        float p = 0.f;
        for (int o = lane; o < HID; o += 32) p += bb[o] * av[o];
        p = warpsum(p);
        if (lane == 0) { if (which) g_vb2[idx] = p; else g_vb1[idx] = p; }
    }
    gbar(1u * nb);

    // ================= P1: scan edge_out (layer-2 edges at LASTN) ===========
    for (int u = gtid; u < NB * NE4; u += nth) {
        int b = (u >= NE4);
        int i4 = b ? u - NE4 : u;
        const int* base = eo + (size_t)b * 2 * NE;
        int4 s = ((const int4*)base)[i4];
        int i = i4 * 4;
        if (s.x == LASTN) k1_hit(b, base, i + 0);
        if (s.y == LASTN) k1_hit(b, base, i + 1);
        if (s.z == LASTN) k1_hit(b, base, i + 2);
        if (s.w == LASTN) k1_hit(b, base, i + 3);
    }
    gbar(2u * nb);

    // ================= P2: scan edge_in (layer-1 edges at S1) ===============
    for (int u = gtid; u < NB * NE4; u += nth) {
        int b = (u >= NE4);
        int i4 = b ? u - NE4 : u;
        const int* base = ei + (size_t)b * 2 * NE;
        int4 s = ((const int4*)base)[i4];
        int i = i4 * 4;
        k2_hit(b, base, i + 0, s.x);
        k2_hit(b, base, i + 1, s.y);
        k2_hit(b, base, i + 2, s.z);
        k2_hit(b, base, i + 3, s.w);
    }
    gbar(3u * nb);

    // ================= P3: ps1/pd1 for all X1 nodes (warp per node) =========
    {
        int c0 = min(g_x1_cnt[0], MAX_X1), c1 = min(g_x1_cnt[1], MAX_X1);
        int tot = c0 + c1, wtot = nb * 8;
        for (int task = gw; task < tot; task += wtot) {
            int b = (task >= c0);
            int x = b ? task - c0 : task;
            int node = g_x1_list[b][x];
            const float4* er = (const float4*)(embed + (size_t)node * INF);
            float4 e0 = er[lane], e1 = er[lane + 32];
#pragma unroll
            for (int idx = 0; idx < 8; idx++) {
                const float4* vr = (const float4*)g_va1[idx];
                float p = dot44(e0, vr[lane]) + dot44(e1, vr[lane + 32]);
                p = warpsum(p);
                if (lane == 0) g_p1[b][x][idx] = p + g_vb1[idx];
            }
        }
    }
    gbar(4u * nb);

    // ================= P4: per-S1-node agg (linear trick) + LN + ELU ========
    {
        int s0 = min(g_s1_cnt[0], MAX_S1), s1c = min(g_s1_cnt[1], MAX_S1);
        for (int task = blockIdx.x; task < s0 + s1c; task += nb) {
            int b = (task >= s0);
            int p = b ? task - s0 : task;
            int node = g_s1_list[b][p];
            int xn = g_x1_idx[b][node];
            float psn[NH];
#pragma unroll
            for (int h = 0; h < NH; h++) psn[h] = g_p1[b][xn][h];
            if (t == 0) s_mcnt = 0;
#pragma unroll
            for (int h = 0; h < NH; h++) s_z[h][t] = 0.f;
            __syncthreads();

            int ecnt = min(g_e1_cnt[b], MAX_E1);
            for (int i = t; i < ecnt; i += 256) {
                if (g_e1_src[b][i] == node) {
                    int d = g_e1_dst[b][i];
                    int xd = g_x1_idx[b][d];
                    int m = atomicAdd(&s_mcnt, 1);
                    if (m < MAX_MATCH) {
                        s_md[m] = d;
#pragma unroll
                        for (int h = 0; h < NH; h++) {
                            float s = psn[h] + g_p1[b][xd][4 + h];
                            float l = s > 0.f ? s : 0.2f * s;
                            s_me[m][h] = __expf(l * INV_SCALE);
                        }
                    }
                }
            }
            __syncthreads();
            int mc = min(s_mcnt, MAX_MATCH);
            if (t < NH) {
                float r = 0.f;
                for (int m = 0; m < mc; m++) r += s_me[m][t];
                s_rsT[t] = r;
                s_rs[t] = (r == 0.f) ? 1.f : r;
            }
            __syncthreads();
            // z_h = sum_m e_mh * embed[dst_m]   (thread t owns dim t)
            for (int m = 0; m < mc; m++) {
                float ev = embed[(size_t)s_md[m] * INF + t];
#pragma unroll
                for (int h = 0; h < NH; h++) s_z[h][t] += s_me[m][h] * ev;
            }
            __syncthreads();
            // hp[h][o] = (z_h . W1[h][o] + rsT_h*b1[h][o]) / rs_h
            for (int oo = 0; oo < 64; oo++) {
                int o512 = wid * 64 + oo;
                int h = o512 >> 7, o = o512 & 127;
                const float4* wr = (const float4*)(W1 + (size_t)(h * HID + o) * INF);
                const float4* zr = (const float4*)s_z[h];
                float pd = dot44(wr[lane], zr[lane]) + dot44(wr[lane + 32], zr[lane + 32]);
                pd = warpsum(pd);
                if (lane == 0)
                    s_ov[o512] = (pd + s_rsT[h] * b1[h * HID + o]) / s_rs[h];
            }
            __syncthreads();
            // LayerNorm(ddof=1, eps on std) + ELU
            float v0 = s_ov[t], v1 = s_ov[t + 256];
            float mean = blockreduce256(v0 + v1, s_red) * (1.f / 512.f);
            float d0 = v0 - mean, d1 = v1 - mean;
            float var = blockreduce256(d0 * d0 + d1 * d1, s_red) * (1.f / 511.f);
            float inv = 1.f / (sqrtf(var) + 1e-6f);
            float y0 = g1[t] * d0 * inv + bn1[t];
            float y1 = g1[t + 256] * d1 * inv + bn1[t + 256];
            y0 = y0 > 0.f ? y0 : __expf(y0) - 1.f;
            y1 = y1 > 0.f ? y1 : __expf(y1) - 1.f;
            g_hln[b][p][t] = y0;
            g_hln[b][p][t + 256] = y1;
            __syncthreads();
        }
    }
    gbar(5u * nb);

    // ================= P5: ps2/pd2 for all S1 nodes (warp per node) =========
    {
        int s0 = min(g_s1_cnt[0], MAX_S1), s1c = min(g_s1_cnt[1], MAX_S1);
        int tot = s0 + s1c, wtot = nb * 8;
        for (int task = gw; task < tot; task += wtot) {
            int b = (task >= s0);
            int p = b ? task - s0 : task;
            const float4* hr = (const float4*)g_hln[b][p];
            float4 x0 = hr[lane], x1 = hr[lane + 32],
                   x2 = hr[lane + 64], x3 = hr[lane + 96];
#pragma unroll
            for (int idx = 0; idx < 8; idx++) {
                const float4* vr = (const float4*)g_va2[idx];
                float pd = dot44(x0, vr[lane]) + dot44(x1, vr[lane + 32])
                         + dot44(x2, vr[lane + 64]) + dot44(x3, vr[lane + 96]);
                pd = warpsum(pd);
                if (lane == 0) g_p2[b][p][idx] = pd + g_vb2[idx];
            }
        }
    }
    gbar(6u * nb);

    // ================= P6: layer-2 agg at LASTN + LN + ReLU + proj ==========
    if (blockIdx.x < NB) {
        int b = blockIdx.x;
        int ec = min(g_d2_cnt[b], MAX_D2);
        float psl[NH];
#pragma unroll
        for (int h = 0; h < NH; h++) psl[h] = g_p2[b][0][h];   // LASTN = s1 idx 0
#pragma unroll
        for (int h = 0; h < NH; h++) { s_z2[h][t] = 0.f; s_z2[h][t + 256] = 0.f; }
        __syncthreads();
        float rsT[NH] = {0.f, 0.f, 0.f, 0.f};
        for (int i = 0; i < ec; i++) {
            int d = g_d2_dst[b][i];
            int pp = g_s1_idx[b][d];
            float e[NH];
#pragma unroll
            for (int h = 0; h < NH; h++) {
                float s = psl[h] + g_p2[b][pp][4 + h];
                float l = s > 0.f ? s : 0.2f * s;
                e[h] = __expf(l * INV_SCALE);
                rsT[h] += e[h];
            }
            const float* hr = g_hln[b][pp];
            float hv0 = hr[t], hv1 = hr[t + 256];
#pragma unroll
            for (int h = 0; h < NH; h++) {
                s_z2[h][t]       += e[h] * hv0;
                s_z2[h][t + 256] += e[h] * hv1;
            }
        }
        __syncthreads();
        float rsc[NH];
#pragma unroll
        for (int h = 0; h < NH; h++) rsc[h] = (rsT[h] == 0.f) ? 1.f : rsT[h];
        for (int oo = 0; oo < 64; oo++) {
            int o512 = wid * 64 + oo;
            int h = o512 >> 7, o = o512 & 127;
            const float4* wr = (const float4*)(W2 + (size_t)(h * HID + o) * HD);
            const float4* zr = (const float4*)s_z2[h];
            float pd = 0.f;
#pragma unroll
            for (int c = 0; c < 4; c++)
                pd += dot44(wr[lane + 32 * c], zr[lane + 32 * c]);
            pd = warpsum(pd);
            if (lane == 0)
                s_hp2[o512] = (pd + rsT[h] * b2[h * HID + o]) / rsc[h];
        }
        __syncthreads();
        float v = 0.f;
        if (t < 128)
            v = 0.25f * (s_hp2[t] + s_hp2[128 + t] + s_hp2[256 + t] + s_hp2[384 + t]);
        float mean = blockreduce256(v, s_red) * (1.f / 128.f);
        float dv = (t < 128) ? v - mean : 0.f;
        float var = blockreduce256(dv * dv, s_red) * (1.f / 127.f);
        float inv = 1.f / (sqrtf(var) + 1e-6f);
        float y = 0.f;
        if (t < 128) {
            y = g2[t] * dv * inv + bn2[t];
            y = y > 0.f ? y : 0.f;
        }
        float c0 = blockreduce256((t < 128) ? y * Vw[t] : 0.f, s_red);
        float c1 = blockreduce256((t < 128) ? y * Vw[HID + t] : 0.f, s_red);
        if (t == 0) {
            out[b * 2 + 0] = c0 + Vb[0];
            out[b * 2 + 1] = c1 + Vb[1];
        }
    }

    // final arrive; last block resets the barrier counter for the next replay
    __syncthreads();
    if (t == 0) {
        __threadfence();
        unsigned old = atomicAdd(&g_bar, 1u);
        if (old == 7u * nb - 1u) atomicExch(&g_bar, 0u);
    }
}

// ------------------------------- launcher ----------------------------------
extern "C" void kernel_launch(void* const* d_in, const int* in_sizes, int n_in,
                              void* d_out, int out_size) {
    const int*   edge_in  = (const int*)d_in[0];
    const int*   edge_out = (const int*)d_in[1];
    const float* embed    = (const float*)d_in[2];
    const float* W1       = (const float*)d_in[3];
    const float* b1       = (const float*)d_in[4];
    const float* a1       = (const float*)d_in[5];
    const float* g1       = (const float*)d_in[6];
    const float* bn1      = (const float*)d_in[7];
    const float* W2       = (const float*)d_in[8];
    const float* b2       = (const float*)d_in[9];
    const float* a2       = (const float*)d_in[10];
    const float* g2       = (const float*)d_in[11];
    const float* bn2      = (const float*)d_in[12];
    const float* Vw       = (const float*)d_in[13];
    const float* Vb       = (const float*)d_in[14];
    float* out = (float*)d_out;

    int nsm = 0;
    cudaDeviceGetAttribute(&nsm, cudaDevAttrMultiProcessorCount, 0);
    if (nsm <= 0) nsm = 132;   // conservative fallback

    fused<<<nsm, 256>>>(edge_in, edge_out, embed, W1, b1, a1, g1, bn1,
                        W2, b2, a2, g2, bn2, Vw, Vb, out);
}

// round 6
// speedup vs baseline: 3.1695x; 2.2959x over previous
#include <cuda_runtime.h>
#include <math.h>

// ---------------------------------------------------------------------------
// GAT_652835029007 — round 6: round-5 structure + 16B alignment fixes.
//   P0 init+va precompute (parallel block groups) -> P1 scan edge_out ->
//   P2 scan edge_in -> P4 per-S1-node attention+agg+LN+ELU (on-demand ps/pd)
//   -> P6 final layer-2 at LASTN (on-demand ps2/pd2) + LN + ReLU + proj.
// 4 grid barriers + final arrive. No X1 set, no p1/p2 globals.
// ---------------------------------------------------------------------------

#define NNODE 20001
#define LASTN 20000
#define INF   256
#define HID   128
#define NH    4
#define HD    512
#define NB    2
#define NE    500000
#define NE4   125000
#define BMW   626
#define MAX_D2    512
#define MAX_E1    65536
#define MAX_S1    1024
#define MAX_MATCH 512
#define INV_SCALE 0.044194173824159216f   // 1/sqrt(512)

// ------------------------------- scratch -----------------------------------
__device__ unsigned g_bar;                 // zero-init; reset by last arriver
__device__ int      g_d2_cnt[NB];
__device__ int      g_d2_dst[NB][MAX_D2];
__device__ unsigned g_s1_bm[NB][BMW];
__device__ int      g_s1_cnt[NB];
__device__ int      g_s1_list[NB][MAX_S1];
__device__ int      g_s1_idx[NB][NNODE];
__device__ int      g_e1_cnt[NB];
__device__ int      g_e1_src[NB][MAX_E1], g_e1_dst[NB][MAX_E1];
__device__ __align__(16) float g_hln[NB][MAX_S1][HD];
__device__ __align__(16) float g_va1[8][INF];   // [h]=src-half, [4+h]=dst-half
__device__ __align__(16) float g_va2[8][HD];
__device__ float    g_vb1[8], g_vb2[8];

// ------------------------------- helpers -----------------------------------
__device__ __forceinline__ float dot44(float4 a, float4 b) {
    return a.x * b.x + a.y * b.y + a.z * b.z + a.w * b.w;
}

__device__ __forceinline__ void warpsum4(float& a, float& b, float& c, float& d) {
#pragma unroll
    for (int off = 16; off; off >>= 1) {
        a += __shfl_xor_sync(0xffffffffu, a, off);
        b += __shfl_xor_sync(0xffffffffu, b, off);
        c += __shfl_xor_sync(0xffffffffu, c, off);
        d += __shfl_xor_sync(0xffffffffu, d, off);
    }
}

__device__ __forceinline__ float blockreduce256(float v, float* sred) {
    int t = threadIdx.x;
    sred[t] = v; __syncthreads();
#pragma unroll
    for (int s = 128; s > 0; s >>= 1) {
        if (t < s) sred[t] += sred[t + s];
        __syncthreads();
    }
    float r = sred[0]; __syncthreads();
    return r;
}

__device__ __forceinline__ void gbar(unsigned target) {
    __syncthreads();
    if (threadIdx.x == 0) {
        __threadfence();
        atomicAdd(&g_bar, 1u);
        while (*(volatile unsigned*)&g_bar < target) __nanosleep(32);
        __threadfence();
    }
    __syncthreads();
}

// ------------------------------- fused kernel -------------------------------
__global__ void __launch_bounds__(256, 2) fused(
    const int* __restrict__ ei, const int* __restrict__ eo,
    const float* __restrict__ embed,
    const float* __restrict__ W1, const float* __restrict__ b1,
    const float* __restrict__ a1,
    const float* __restrict__ g1, const float* __restrict__ bn1,
    const float* __restrict__ W2, const float* __restrict__ b2,
    const float* __restrict__ a2,
    const float* __restrict__ g2, const float* __restrict__ bn2,
    const float* __restrict__ Vw, const float* __restrict__ Vb,
    float* __restrict__ out)
{
    int t = threadIdx.x;
    int lane = t & 31, wid = t >> 5;
    unsigned nb = gridDim.x;
    int bi = blockIdx.x;
    int gtid = bi * 256 + t;
    int nth = nb * 256;

    __shared__ __align__(16) float s_red[256];
    __shared__ float s_rs[NH], s_rsT[NH];
    __shared__ int   s_mcnt;
    __shared__ __align__(16) float s_va1[8][INF];        // 8KB, P4 only
    __shared__ float s_vb1s[8];
    __shared__ __align__(16) char s_mem[20480];
    // P4 views (all offsets multiples of 16)
    int*   s_md = (int*)s_mem;                           // [512]      2KB
    float (*s_me)[NH] = (float(*)[NH])(s_mem + 2048);    // [512][4]   8KB
    float (*s_z)[INF] = (float(*)[INF])(s_mem + 10240);  // [4][256]   4KB
    float* s_ov = (float*)(s_mem + 14336);               // [512]      2KB
    // P6 views
    float (*s_z2)[HD] = (float(*)[HD])(s_mem);           // [4][512]   8KB
    float (*s_e2)[NH] = (float(*)[NH])(s_mem + 8192);    // [512][4]   8KB
    int*   s_md2 = (int*)(s_mem + 16384);                // [512]      2KB
    float* s_hp2 = s_ov;                                 // [512] (disjoint: 14336..16384)

    // ===================== P0: parallel init + precompute ===================
    if (bi < 8) {
        // va1: item = gtid in [0, 2048)
        int idx = gtid >> 8, k = gtid & 255;
        int h = idx & 3, sd = idx >> 2;
        const float* W = W1 + (size_t)h * HID * INF + k;
        const float* av = a1 + h * 2 * HID + sd * HID;
        float a0 = 0.f, a1_ = 0.f, a2_ = 0.f, a3 = 0.f;
#pragma unroll 8
        for (int o = 0; o < HID; o += 4) {
            a0 += W[(o + 0) * INF] * av[o + 0];
            a1_ += W[(o + 1) * INF] * av[o + 1];
            a2_ += W[(o + 2) * INF] * av[o + 2];
            a3 += W[(o + 3) * INF] * av[o + 3];
        }
        g_va1[idx][k] = (a0 + a1_) + (a2_ + a3);
    } else if (bi < 24) {
        // va2: item = (bi-8)*256+t in [0, 4096)
        int u = (bi - 8) * 256 + t;
        int idx = u >> 9, k = u & 511;
        int h = idx & 3, sd = idx >> 2;
        const float* W = W2 + (size_t)h * HID * HD + k;
        const float* av = a2 + h * 2 * HID + sd * HID;
        float a0 = 0.f, a1_ = 0.f, a2_ = 0.f, a3 = 0.f;
#pragma unroll 8
        for (int o = 0; o < HID; o += 4) {
            a0 += W[(o + 0) * HD] * av[o + 0];
            a1_ += W[(o + 1) * HD] * av[o + 1];
            a2_ += W[(o + 2) * HD] * av[o + 2];
            a3 += W[(o + 3) * HD] * av[o + 3];
        }
        g_va2[idx][k] = (a0 + a1_) + (a2_ + a3);
    } else if (bi == 24 || bi == 25) {
        // vb1 / vb2: warp w -> idx w
        int which = (bi == 25);
        int idx = wid, h = idx & 3, sd = idx >> 2;
        const float* bb = (which ? b2 : b1) + h * HID;
        const float* av = (which ? a2 : a1) + h * 2 * HID + sd * HID;
        float p = 0.f;
        for (int o = lane; o < HID; o += 32) p += bb[o] * av[o];
#pragma unroll
        for (int off = 16; off; off >>= 1) p += __shfl_xor_sync(0xffffffffu, p, off);
        if (lane == 0) { if (which) g_vb2[idx] = p; else g_vb1[idx] = p; }
    } else if (bi < 31) {
        // s1 bitmap init: i = (bi-26)*256+t over NB*BMW = 1252
        int i = (bi - 26) * 256 + t;
        if (i < NB * BMW) {
            int b = i / BMW, w = i - b * BMW;
            g_s1_bm[b][w] = (w == (LASTN >> 5)) ? (1u << (LASTN & 31)) : 0u;
        }
    } else if (bi == 31 && t == 0) {
        for (int b = 0; b < NB; b++) {
            g_d2_cnt[b] = 0; g_e1_cnt[b] = 0;
            g_s1_cnt[b] = 1;
            g_s1_list[b][0] = LASTN; g_s1_idx[b][LASTN] = 0;
        }
    }
    gbar(1u * nb);

    // ===================== P1: scan edge_out for src == LASTN ===============
    for (int u = gtid; u < NB * NE4; u += nth) {
        int b = (u >= NE4);
        int i4 = b ? u - NE4 : u;
        const int* base = eo + (size_t)b * 2 * NE;
        int4 s = ((const int4*)base)[i4];
        int i = i4 * 4;
#pragma unroll
        for (int j = 0; j < 4; j++) {
            int sv = (j == 0) ? s.x : (j == 1) ? s.y : (j == 2) ? s.z : s.w;
            if (sv == LASTN) {
                int dst = base[NE + i + j];
                int p = atomicAdd(&g_d2_cnt[b], 1);
                if (p < MAX_D2) g_d2_dst[b][p] = dst;
                unsigned m = 1u << (dst & 31);
                unsigned old = atomicOr(&g_s1_bm[b][dst >> 5], m);
                if (!(old & m)) {
                    int q = atomicAdd(&g_s1_cnt[b], 1);
                    if (q < MAX_S1) { g_s1_list[b][q] = dst; g_s1_idx[b][dst] = q; }
                }
            }
        }
    }
    gbar(2u * nb);

    // ===================== P2: scan edge_in for src in S1 ===================
    for (int u = gtid; u < NB * NE4; u += nth) {
        int b = (u >= NE4);
        int i4 = b ? u - NE4 : u;
        const int* base = ei + (size_t)b * 2 * NE;
        int4 s = ((const int4*)base)[i4];
        int i = i4 * 4;
#pragma unroll
        for (int j = 0; j < 4; j++) {
            int sv = (j == 0) ? s.x : (j == 1) ? s.y : (j == 2) ? s.z : s.w;
            if ((g_s1_bm[b][sv >> 5] >> (sv & 31)) & 1u) {
                int p = atomicAdd(&g_e1_cnt[b], 1);
                if (p < MAX_E1) {
                    g_e1_src[b][p] = sv;
                    g_e1_dst[b][p] = base[NE + i + j];
                }
            }
        }
    }
    gbar(3u * nb);

    // ===================== P4: per-S1-node agg + LN + ELU ===================
    {
        // preload va1 + vb1 into shared (once)
        for (int u = t; u < 8 * INF; u += 256)
            ((float*)s_va1)[u] = ((const float*)g_va1)[u];
        if (t < 8) s_vb1s[t] = g_vb1[t];
        __syncthreads();

        int s0 = min(g_s1_cnt[0], MAX_S1), s1c = min(g_s1_cnt[1], MAX_S1);
        int tot = s0 + s1c;
        int h = wid >> 1;   // head owned by this warp in the matvec (const)

        for (int task = bi; task < tot; task += nb) {
            int b = (task >= s0);
            int p = b ? task - s0 : task;
            int node = g_s1_list[b][p];
            if (t == 0) s_mcnt = 0;
            __syncthreads();

            // match scan
            int ecnt = min(g_e1_cnt[b], MAX_E1);
            for (int i = t; i < ecnt; i += 256) {
                if (g_e1_src[b][i] == node) {
                    int m = atomicAdd(&s_mcnt, 1);
                    if (m < MAX_MATCH) s_md[m] = g_e1_dst[b][i];
                }
            }
            __syncthreads();
            int mc = min(s_mcnt, MAX_MATCH);

            // psn (per-warp redundant): ps1[node][h] = emb.va1[h] + vb1[h]
            float p0, p1, p2, p3;
            {
                const float4* er = (const float4*)(embed + (size_t)node * INF);
                float4 e0 = er[lane], e1 = er[lane + 32];
                p0 = dot44(e0, ((float4*)s_va1[0])[lane]) + dot44(e1, ((float4*)s_va1[0])[lane + 32]);
                p1 = dot44(e0, ((float4*)s_va1[1])[lane]) + dot44(e1, ((float4*)s_va1[1])[lane + 32]);
                p2 = dot44(e0, ((float4*)s_va1[2])[lane]) + dot44(e1, ((float4*)s_va1[2])[lane + 32]);
                p3 = dot44(e0, ((float4*)s_va1[3])[lane]) + dot44(e1, ((float4*)s_va1[3])[lane + 32]);
                warpsum4(p0, p1, p2, p3);
                p0 += s_vb1s[0]; p1 += s_vb1s[1]; p2 += s_vb1s[2]; p3 += s_vb1s[3];
            }

            // per-match attention weights (warps parallel over matches)
            for (int m = wid; m < mc; m += 8) {
                int d = s_md[m];
                const float4* dr = (const float4*)(embed + (size_t)d * INF);
                float4 d0 = dr[lane], d1 = dr[lane + 32];
                float q0 = dot44(d0, ((float4*)s_va1[4])[lane]) + dot44(d1, ((float4*)s_va1[4])[lane + 32]);
                float q1 = dot44(d0, ((float4*)s_va1[5])[lane]) + dot44(d1, ((float4*)s_va1[5])[lane + 32]);
                float q2 = dot44(d0, ((float4*)s_va1[6])[lane]) + dot44(d1, ((float4*)s_va1[6])[lane + 32]);
                float q3 = dot44(d0, ((float4*)s_va1[7])[lane]) + dot44(d1, ((float4*)s_va1[7])[lane + 32]);
                warpsum4(q0, q1, q2, q3);
                if (lane == 0) {
                    float s, l;
                    s = p0 + q0 + s_vb1s[4]; l = s > 0.f ? s : 0.2f * s; s_me[m][0] = __expf(l * INV_SCALE);
                    s = p1 + q1 + s_vb1s[5]; l = s > 0.f ? s : 0.2f * s; s_me[m][1] = __expf(l * INV_SCALE);
                    s = p2 + q2 + s_vb1s[6]; l = s > 0.f ? s : 0.2f * s; s_me[m][2] = __expf(l * INV_SCALE);
                    s = p3 + q3 + s_vb1s[7]; l = s > 0.f ? s : 0.2f * s; s_me[m][3] = __expf(l * INV_SCALE);
                }
            }
            __syncthreads();

            // rowsums
            if (t < NH) {
                float r = 0.f;
                for (int m = 0; m < mc; m++) r += s_me[m][t];
                s_rsT[t] = r;
                s_rs[t] = (r == 0.f) ? 1.f : r;
            }
            // z_h[t] = sum_m e_mh * embed[dst_m][t]  (register accumulators)
            float z0 = 0.f, z1 = 0.f, z2 = 0.f, z3 = 0.f;
            for (int m = 0; m < mc; m++) {
                float ev = embed[(size_t)s_md[m] * INF + t];   // L1-warm
                float4 me = *(const float4*)s_me[m];
                z0 += me.x * ev; z1 += me.y * ev; z2 += me.z * ev; z3 += me.w * ev;
            }
            s_z[0][t] = z0; s_z[1][t] = z1; s_z[2][t] = z2; s_z[3][t] = z3;
            __syncthreads();

            // matvec: hp[o512] = (z_h . W1row + rsT_h*b1) / rs_h, 4 outs/iter
            float rsT = s_rsT[h], invrs = 1.f / s_rs[h];
            const float4* z4 = (const float4*)s_z[h];
            float4 za = z4[lane], zb = z4[lane + 32];
            for (int og = 0; og < 64; og += 4) {
                int obase = wid * 64 + og;
                int o = obase & 127;
                const float4* w0 = (const float4*)(W1 + (size_t)(h * HID + o + 0) * INF);
                const float4* w1 = (const float4*)(W1 + (size_t)(h * HID + o + 1) * INF);
                const float4* w2 = (const float4*)(W1 + (size_t)(h * HID + o + 2) * INF);
                const float4* w3 = (const float4*)(W1 + (size_t)(h * HID + o + 3) * INF);
                float v0 = dot44(w0[lane], za) + dot44(w0[lane + 32], zb);
                float v1 = dot44(w1[lane], za) + dot44(w1[lane + 32], zb);
                float v2 = dot44(w2[lane], za) + dot44(w2[lane + 32], zb);
                float v3 = dot44(w3[lane], za) + dot44(w3[lane + 32], zb);
                warpsum4(v0, v1, v2, v3);
                if (lane == 0) {
                    const float* bb = b1 + h * HID + o;
                    s_ov[obase + 0] = (v0 + rsT * bb[0]) * invrs;
                    s_ov[obase + 1] = (v1 + rsT * bb[1]) * invrs;
                    s_ov[obase + 2] = (v2 + rsT * bb[2]) * invrs;
                    s_ov[obase + 3] = (v3 + rsT * bb[3]) * invrs;
                }
            }
            __syncthreads();

            // LayerNorm(ddof=1, eps on std) + ELU
            float v0 = s_ov[t], v1 = s_ov[t + 256];
            float mean = blockreduce256(v0 + v1, s_red) * (1.f / 512.f);
            float d0 = v0 - mean, d1 = v1 - mean;
            float var = blockreduce256(d0 * d0 + d1 * d1, s_red) * (1.f / 511.f);
            float inv = 1.f / (sqrtf(var) + 1e-6f);
            float y0 = g1[t] * d0 * inv + bn1[t];
            float y1 = g1[t + 256] * d1 * inv + bn1[t + 256];
            y0 = y0 > 0.f ? y0 : __expf(y0) - 1.f;
            y1 = y1 > 0.f ? y1 : __expf(y1) - 1.f;
            g_hln[b][p][t] = y0;
            g_hln[b][p][t + 256] = y1;
            __syncthreads();
        }
    }
    gbar(4u * nb);

    // ===================== P6: final layer-2 at LASTN =======================
    if (bi < NB) {
        int b = bi;
        int ec = min(g_d2_cnt[b], MAX_D2);
        int h = wid >> 1;

        // ps2[LASTN] per warp (s1 idx 0)
        float r0, r1, r2, r3;
        {
            const float4* hr = (const float4*)g_hln[b][0];
            float4 x0 = hr[lane], x1 = hr[lane + 32], x2 = hr[lane + 64], x3 = hr[lane + 96];
            const float4* v0p = (const float4*)g_va2[0];
            const float4* v1p = (const float4*)g_va2[1];
            const float4* v2p = (const float4*)g_va2[2];
            const float4* v3p = (const float4*)g_va2[3];
            r0 = dot44(x0, v0p[lane]) + dot44(x1, v0p[lane + 32]) + dot44(x2, v0p[lane + 64]) + dot44(x3, v0p[lane + 96]);
            r1 = dot44(x0, v1p[lane]) + dot44(x1, v1p[lane + 32]) + dot44(x2, v1p[lane + 64]) + dot44(x3, v1p[lane + 96]);
            r2 = dot44(x0, v2p[lane]) + dot44(x1, v2p[lane + 32]) + dot44(x2, v2p[lane + 64]) + dot44(x3, v2p[lane + 96]);
            r3 = dot44(x0, v3p[lane]) + dot44(x1, v3p[lane + 32]) + dot44(x2, v3p[lane + 64]) + dot44(x3, v3p[lane + 96]);
            warpsum4(r0, r1, r2, r3);
            r0 += g_vb2[0]; r1 += g_vb2[1]; r2 += g_vb2[2]; r3 += g_vb2[3];
        }

        // per-edge weights (warps parallel)
        for (int i = wid; i < ec; i += 8) {
            int d = g_d2_dst[b][i];
            int pd = g_s1_idx[b][d];
            const float4* hr = (const float4*)g_hln[b][pd];
            float4 x0 = hr[lane], x1 = hr[lane + 32], x2 = hr[lane + 64], x3 = hr[lane + 96];
            const float4* v4p = (const float4*)g_va2[4];
            const float4* v5p = (const float4*)g_va2[5];
            const float4* v6p = (const float4*)g_va2[6];
            const float4* v7p = (const float4*)g_va2[7];
            float q0 = dot44(x0, v4p[lane]) + dot44(x1, v4p[lane + 32]) + dot44(x2, v4p[lane + 64]) + dot44(x3, v4p[lane + 96]);
            float q1 = dot44(x0, v5p[lane]) + dot44(x1, v5p[lane + 32]) + dot44(x2, v5p[lane + 64]) + dot44(x3, v5p[lane + 96]);
            float q2 = dot44(x0, v6p[lane]) + dot44(x1, v6p[lane + 32]) + dot44(x2, v6p[lane + 64]) + dot44(x3, v6p[lane + 96]);
            float q3 = dot44(x0, v7p[lane]) + dot44(x1, v7p[lane + 32]) + dot44(x2, v7p[lane + 64]) + dot44(x3, v7p[lane + 96]);
            warpsum4(q0, q1, q2, q3);
            if (lane == 0) {
                s_md2[i] = pd;
                float s, l;
                s = r0 + q0 + g_vb2[4]; l = s > 0.f ? s : 0.2f * s; s_e2[i][0] = __expf(l * INV_SCALE);
                s = r1 + q1 + g_vb2[5]; l = s > 0.f ? s : 0.2f * s; s_e2[i][1] = __expf(l * INV_SCALE);
                s = r2 + q2 + g_vb2[6]; l = s > 0.f ? s : 0.2f * s; s_e2[i][2] = __expf(l * INV_SCALE);
                s = r3 + q3 + g_vb2[7]; l = s > 0.f ? s : 0.2f * s; s_e2[i][3] = __expf(l * INV_SCALE);
            }
        }
        __syncthreads();

        // rowsums
        if (t < NH) {
            float r = 0.f;
            for (int i = 0; i < ec; i++) r += s_e2[i][t];
            s_rsT[t] = r;
            s_rs[t] = (r == 0.f) ? 1.f : r;
        }
        // z2_h = sum e * hln[dst]  (thread owns dims t and t+256)
        float za0 = 0.f, za1 = 0.f, za2 = 0.f, za3 = 0.f;
        float zb0 = 0.f, zb1 = 0.f, zb2 = 0.f, zb3 = 0.f;
        for (int i = 0; i < ec; i++) {
            int pd = s_md2[i];
            float hv0 = g_hln[b][pd][t];
            float hv1 = g_hln[b][pd][t + 256];
            float4 me = *(const float4*)s_e2[i];
            za0 += me.x * hv0; za1 += me.y * hv0; za2 += me.z * hv0; za3 += me.w * hv0;
            zb0 += me.x * hv1; zb1 += me.y * hv1; zb2 += me.z * hv1; zb3 += me.w * hv1;
        }
        s_z2[0][t] = za0; s_z2[1][t] = za1; s_z2[2][t] = za2; s_z2[3][t] = za3;
        s_z2[0][t + 256] = zb0; s_z2[1][t + 256] = zb1; s_z2[2][t + 256] = zb2; s_z2[3][t + 256] = zb3;
        __syncthreads();

        // matvec dot-512 per output (4 outs/iter per warp)
        float rsT = s_rsT[h], invrs = 1.f / s_rs[h];
        const float4* z4 = (const float4*)s_z2[h];
        float4 zc0 = z4[lane], zc1 = z4[lane + 32], zc2 = z4[lane + 64], zc3 = z4[lane + 96];
        for (int og = 0; og < 64; og += 4) {
            int obase = wid * 64 + og;
            int o = obase & 127;
            float v[4];
#pragma unroll
            for (int j = 0; j < 4; j++) {
                const float4* wr = (const float4*)(W2 + (size_t)(h * HID + o + j) * HD);
                v[j] = dot44(wr[lane], zc0) + dot44(wr[lane + 32], zc1)
                     + dot44(wr[lane + 64], zc2) + dot44(wr[lane + 96], zc3);
            }
            warpsum4(v[0], v[1], v[2], v[3]);
            if (lane == 0) {
                const float* bb = b2 + h * HID + o;
                s_hp2[obase + 0] = (v[0] + rsT * bb[0]) * invrs;
                s_hp2[obase + 1] = (v[1] + rsT * bb[1]) * invrs;
                s_hp2[obase + 2] = (v[2] + rsT * bb[2]) * invrs;
                s_hp2[obase + 3] = (v[3] + rsT * bb[3]) * invrs;
            }
        }
        __syncthreads();

        // mean over heads + LN(128) + ReLU + projection
        float v = 0.f;
        if (t < 128)
            v = 0.25f * (s_hp2[t] + s_hp2[128 + t] + s_hp2[256 + t] + s_hp2[384 + t]);
        float mean = blockreduce256(v, s_red) * (1.f / 128.f);
        float dv = (t < 128) ? v - mean : 0.f;
        float var = blockreduce256(dv * dv, s_red) * (1.f / 127.f);
        float inv = 1.f / (sqrtf(var) + 1e-6f);
        float y = 0.f;
        if (t < 128) {
            y = g2[t] * dv * inv + bn2[t];
            y = y > 0.f ? y : 0.f;
        }
        float c0 = blockreduce256((t < 128) ? y * Vw[t] : 0.f, s_red);
        float c1 = blockreduce256((t < 128) ? y * Vw[HID + t] : 0.f, s_red);
        if (t == 0) {
            out[b * 2 + 0] = c0 + Vb[0];
            out[b * 2 + 1] = c1 + Vb[1];
        }
    }

    // final arrive; last block resets barrier for the next graph replay
    __syncthreads();
    if (t == 0) {
        __threadfence();
        unsigned old = atomicAdd(&g_bar, 1u);
        if (old == 5u * nb - 1u) atomicExch(&g_bar, 0u);
    }
}

// ------------------------------- launcher ----------------------------------
extern "C" void kernel_launch(void* const* d_in, const int* in_sizes, int n_in,
                              void* d_out, int out_size) {
    const int*   edge_in  = (const int*)d_in[0];
    const int*   edge_out = (const int*)d_in[1];
    const float* embed    = (const float*)d_in[2];
    const float* W1       = (const float*)d_in[3];
    const float* b1       = (const float*)d_in[4];
    const float* a1       = (const float*)d_in[5];
    const float* g1       = (const float*)d_in[6];
    const float* bn1      = (const float*)d_in[7];
    const float* W2       = (const float*)d_in[8];
    const float* b2       = (const float*)d_in[9];
    const float* a2       = (const float*)d_in[10];
    const float* g2       = (const float*)d_in[11];
    const float* bn2      = (const float*)d_in[12];
    const float* Vw       = (const float*)d_in[13];
    const float* Vb       = (const float*)d_in[14];
    float* out = (float*)d_out;

    int nsm = 0;
    cudaDeviceGetAttribute(&nsm, cudaDevAttrMultiProcessorCount, 0);
    if (nsm <= 0) nsm = 132;
    int occ = 0;
    cudaOccupancyMaxActiveBlocksPerMultiprocessor(&occ, fused, 256, 0);
    if (occ < 1) occ = 1;
    if (occ > 2) occ = 2;

    fused<<<nsm * occ, 256>>>(edge_in, edge_out, embed, W1, b1, a1, g1, bn1,
                              W2, b2, a2, g2, bn2, Vw, Vb, out);
}